// round 1
// baseline (speedup 1.0000x reference)
#include <cuda_runtime.h>
#include <math.h>

#define Bb  2
#define Ss  4096
#define Dd  768
#define Hh  12
#define HDd 64
#define Mm  (Bb*Ss)   // 8192

// Scratch: head-split projections [B*H][S][64] and concat attention output [B,S,D]
__device__ float g_Q[(size_t)Bb*Hh*Ss*HDd];
__device__ float g_K[(size_t)Bb*Hh*Ss*HDd];
__device__ float g_V[(size_t)Bb*Hh*Ss*HDd];
__device__ float g_F[(size_t)Bb*Ss*Dd];

// ---------------------------------------------------------------------------
// Generic SGEMM: C[M=8192, N=768] = X[M,768] @ W[N=768,768]^T + bias
// split=1: write out[((b*H + n/64)*S + s)*64 + n%64]   (head-split)
// split=0: write out[m*768 + n]                         (row-major)
// ---------------------------------------------------------------------------
__global__ __launch_bounds__(256) void gemm_kernel(const float* __restrict__ X,
                                                   const float* __restrict__ W,
                                                   const float* __restrict__ bias,
                                                   float* __restrict__ out,
                                                   int split)
{
    __shared__ float Xs[16][68];
    __shared__ float Ws[16][68];

    const int tid = threadIdx.x;
    const int tx  = tid & 15;        // 0..15 -> n micro
    const int ty  = tid >> 4;        // 0..15 -> m micro
    const int n0  = blockIdx.x * 64;
    const int m0  = blockIdx.y * 64;

    const int lr = tid >> 2;         // 0..63 row to load
    const int lk = (tid & 3) * 4;    // k offset {0,4,8,12}

    float acc[4][4] = {};

    for (int k0 = 0; k0 < Dd; k0 += 16) {
        float4 xv = *(const float4*)&X[(size_t)(m0 + lr) * Dd + k0 + lk];
        float4 wv = *(const float4*)&W[(size_t)(n0 + lr) * Dd + k0 + lk];
        Xs[lk+0][lr] = xv.x; Xs[lk+1][lr] = xv.y;
        Xs[lk+2][lr] = xv.z; Xs[lk+3][lr] = xv.w;
        Ws[lk+0][lr] = wv.x; Ws[lk+1][lr] = wv.y;
        Ws[lk+2][lr] = wv.z; Ws[lk+3][lr] = wv.w;
        __syncthreads();

        #pragma unroll
        for (int kk = 0; kk < 16; kk++) {
            float4 a = *(const float4*)&Xs[kk][ty * 4];
            float4 b = *(const float4*)&Ws[kk][tx * 4];
            acc[0][0] = fmaf(a.x, b.x, acc[0][0]);
            acc[0][1] = fmaf(a.x, b.y, acc[0][1]);
            acc[0][2] = fmaf(a.x, b.z, acc[0][2]);
            acc[0][3] = fmaf(a.x, b.w, acc[0][3]);
            acc[1][0] = fmaf(a.y, b.x, acc[1][0]);
            acc[1][1] = fmaf(a.y, b.y, acc[1][1]);
            acc[1][2] = fmaf(a.y, b.z, acc[1][2]);
            acc[1][3] = fmaf(a.y, b.w, acc[1][3]);
            acc[2][0] = fmaf(a.z, b.x, acc[2][0]);
            acc[2][1] = fmaf(a.z, b.y, acc[2][1]);
            acc[2][2] = fmaf(a.z, b.z, acc[2][2]);
            acc[2][3] = fmaf(a.z, b.w, acc[2][3]);
            acc[3][0] = fmaf(a.w, b.x, acc[3][0]);
            acc[3][1] = fmaf(a.w, b.y, acc[3][1]);
            acc[3][2] = fmaf(a.w, b.z, acc[3][2]);
            acc[3][3] = fmaf(a.w, b.w, acc[3][3]);
        }
        __syncthreads();
    }

    const float4 bv = *(const float4*)&bias[n0 + tx * 4];
    if (split) {
        const int h = n0 >> 6;   // whole 64-tile lies in one head
        #pragma unroll
        for (int i = 0; i < 4; i++) {
            int mrow = m0 + ty * 4 + i;
            int b    = mrow >> 12;        // /4096
            int srow = mrow & 4095;
            float4 r = make_float4(acc[i][0] + bv.x, acc[i][1] + bv.y,
                                   acc[i][2] + bv.z, acc[i][3] + bv.w);
            *(float4*)&out[(((size_t)(b * Hh + h)) * Ss + srow) * 64 + tx * 4] = r;
        }
    } else {
        #pragma unroll
        for (int i = 0; i < 4; i++) {
            int mrow = m0 + ty * 4 + i;
            float4 r = make_float4(acc[i][0] + bv.x, acc[i][1] + bv.y,
                                   acc[i][2] + bv.z, acc[i][3] + bv.w);
            *(float4*)&out[(size_t)mrow * Dd + n0 + tx * 4] = r;
        }
    }
}

// ---------------------------------------------------------------------------
// Causal flash attention: one block per (q-tile of 64 rows, b*h).
// 64 threads; each thread owns one query row -> softmax state is thread-local.
// ---------------------------------------------------------------------------
__global__ __launch_bounds__(64) void attn_kernel(const float* __restrict__ Qh,
                                                  const float* __restrict__ Kh,
                                                  const float* __restrict__ Vh,
                                                  float* __restrict__ feats)
{
    __shared__ float4 Ks[64 * 16];     // 16 KB  [row][d4]
    __shared__ float4 Vs[64 * 16];     // 16 KB
    __shared__ float  Srow[64][64];    // 16 KB  [c][tid] lane-indexed: conflict-free

    const int qt  = gridDim.x - 1 - blockIdx.x;  // heavy tiles first
    const int bh  = blockIdx.y;
    const int tid = threadIdx.x;
    const int sq  = qt * 64 + tid;
    const float NEG = -1e30f;

    float qr[64], o[64];
    const float4* qsrc = (const float4*)(Qh + ((size_t)bh * Ss + sq) * 64);
    #pragma unroll
    for (int d = 0; d < 16; d++) {
        float4 t = qsrc[d];
        qr[4*d+0] = t.x * 0.125f; qr[4*d+1] = t.y * 0.125f;
        qr[4*d+2] = t.z * 0.125f; qr[4*d+3] = t.w * 0.125f;
        o[4*d+0] = 0.f; o[4*d+1] = 0.f; o[4*d+2] = 0.f; o[4*d+3] = 0.f;
    }

    float m = NEG, l = 0.f;
    const float4* kbase = (const float4*)(Kh + (size_t)bh * Ss * 64);
    const float4* vbase = (const float4*)(Vh + (size_t)bh * Ss * 64);

    for (int kt = 0; kt <= qt; kt++) {
        const float4* ks = kbase + kt * 64 * 16;
        const float4* vs = vbase + kt * 64 * 16;
        #pragma unroll
        for (int i = 0; i < 16; i++) {   // tile is 16 KB contiguous: coalesced
            Ks[i * 64 + tid] = ks[i * 64 + tid];
            Vs[i * 64 + tid] = vs[i * 64 + tid];
        }
        __syncthreads();

        const bool diag = (kt == qt);
        float tmax = NEG;
        for (int c = 0; c < 64; c++) {
            float sum = 0.f;
            #pragma unroll
            for (int d = 0; d < 16; d++) {
                float4 kv = Ks[c * 16 + d];   // broadcast across lanes
                sum = fmaf(qr[4*d+0], kv.x, sum);
                sum = fmaf(qr[4*d+1], kv.y, sum);
                sum = fmaf(qr[4*d+2], kv.z, sum);
                sum = fmaf(qr[4*d+3], kv.w, sum);
            }
            if (diag && c > tid) sum = NEG;   // causal mask on diagonal tile
            Srow[c][tid] = sum;
            tmax = fmaxf(tmax, sum);
        }

        float mn   = fmaxf(m, tmax);
        float corr = __expf(m - mn);
        l *= corr;
        #pragma unroll
        for (int d = 0; d < 64; d++) o[d] *= corr;

        for (int c = 0; c < 64; c++) {
            float p = __expf(Srow[c][tid] - mn);   // masked -> exp(-huge)=0
            l += p;
            #pragma unroll
            for (int d = 0; d < 16; d++) {
                float4 v = Vs[c * 16 + d];
                o[4*d+0] = fmaf(p, v.x, o[4*d+0]);
                o[4*d+1] = fmaf(p, v.y, o[4*d+1]);
                o[4*d+2] = fmaf(p, v.z, o[4*d+2]);
                o[4*d+3] = fmaf(p, v.w, o[4*d+3]);
            }
        }
        m = mn;
        __syncthreads();
    }

    const float inv = 1.f / l;
    const int b = bh / Hh, h = bh - b * Hh;
    float4* dst = (float4*)(feats + ((size_t)b * Ss + sq) * Dd + h * 64);
    #pragma unroll
    for (int d = 0; d < 16; d++)
        dst[d] = make_float4(o[4*d+0] * inv, o[4*d+1] * inv,
                             o[4*d+2] * inv, o[4*d+3] * inv);
}

// ---------------------------------------------------------------------------
extern "C" void kernel_launch(void* const* d_in, const int* in_sizes, int n_in,
                              void* d_out, int out_size)
{
    const float* q  = (const float*)d_in[0];
    const float* k  = (const float*)d_in[1];
    const float* v  = (const float*)d_in[2];
    // d_in[3] = mask (causal by construction; handled analytically)
    const float* Wq = (const float*)d_in[4];
    const float* bq = (const float*)d_in[5];
    const float* Wk = (const float*)d_in[6];
    const float* bk = (const float*)d_in[7];
    const float* Wv = (const float*)d_in[8];
    const float* bv = (const float*)d_in[9];
    const float* Wo = (const float*)d_in[10];
    const float* bo = (const float*)d_in[11];
    float* out = (float*)d_out;

    float *gq, *gk, *gv, *gf;
    cudaGetSymbolAddress((void**)&gq, g_Q);
    cudaGetSymbolAddress((void**)&gk, g_K);
    cudaGetSymbolAddress((void**)&gv, g_V);
    cudaGetSymbolAddress((void**)&gf, g_F);

    dim3 gg(Dd / 64, Mm / 64);        // (12, 128)
    gemm_kernel<<<gg, 256>>>(q, Wq, bq, gq, 1);
    gemm_kernel<<<gg, 256>>>(k, Wk, bk, gk, 1);
    gemm_kernel<<<gg, 256>>>(v, Wv, bv, gv, 1);

    attn_kernel<<<dim3(Ss / 64, Bb * Hh), 64>>>(gq, gk, gv, gf);

    gemm_kernel<<<gg, 256>>>(gf, Wo, bo, out, 0);
}

// round 2
// speedup vs baseline: 2.1661x; 2.1661x over previous
#include <cuda_runtime.h>
#include <math.h>
#include <stdint.h>

#define Bb  2
#define Ss  4096
#define Dd  768
#define Hh  12
#define Mm  (Bb*Ss)   // 8192

// Scratch: head-split projections [B*H][S][64] and concat attention output [B,S,D]
__device__ float g_Q[(size_t)Bb*Hh*Ss*64];
__device__ float g_K[(size_t)Bb*Hh*Ss*64];
__device__ float g_V[(size_t)Bb*Hh*Ss*64];
__device__ float g_F[(size_t)Bb*Ss*Dd];

// ---------------------------------------------------------------------------
// helpers
// ---------------------------------------------------------------------------
__device__ __forceinline__ float to_tf32(float x) {
    uint32_t u;
    asm("cvt.rna.tf32.f32 %0, %1;" : "=r"(u) : "f"(x));
    return __uint_as_float(u);
}

__device__ __forceinline__ void mma_tf32(float c[4],
                                         uint32_t a0, uint32_t a1, uint32_t a2, uint32_t a3,
                                         uint32_t b0, uint32_t b1) {
    asm volatile(
        "mma.sync.aligned.m16n8k8.row.col.f32.tf32.tf32.f32 "
        "{%0,%1,%2,%3}, {%4,%5,%6,%7}, {%8,%9}, {%0,%1,%2,%3};\n"
        : "+f"(c[0]), "+f"(c[1]), "+f"(c[2]), "+f"(c[3])
        : "r"(a0), "r"(a1), "r"(a2), "r"(a3), "r"(b0), "r"(b1));
}

// ---------------------------------------------------------------------------
// Generic SGEMM: C[M=8192, N=768] = X[M,768] @ W[N=768,768]^T + bias
// split=1: head-split layout; split=0: row-major
// ---------------------------------------------------------------------------
__global__ __launch_bounds__(256) void gemm_kernel(const float* __restrict__ X,
                                                   const float* __restrict__ W,
                                                   const float* __restrict__ bias,
                                                   float* __restrict__ out,
                                                   int split)
{
    __shared__ float Xs[16][68];
    __shared__ float Ws[16][68];

    const int tid = threadIdx.x;
    const int tx  = tid & 15;
    const int ty  = tid >> 4;
    const int n0  = blockIdx.x * 64;
    const int m0  = blockIdx.y * 64;

    const int lr = tid >> 2;
    const int lk = (tid & 3) * 4;

    float acc[4][4] = {};

    for (int k0 = 0; k0 < Dd; k0 += 16) {
        float4 xv = *(const float4*)&X[(size_t)(m0 + lr) * Dd + k0 + lk];
        float4 wv = *(const float4*)&W[(size_t)(n0 + lr) * Dd + k0 + lk];
        Xs[lk+0][lr] = xv.x; Xs[lk+1][lr] = xv.y;
        Xs[lk+2][lr] = xv.z; Xs[lk+3][lr] = xv.w;
        Ws[lk+0][lr] = wv.x; Ws[lk+1][lr] = wv.y;
        Ws[lk+2][lr] = wv.z; Ws[lk+3][lr] = wv.w;
        __syncthreads();

        #pragma unroll
        for (int kk = 0; kk < 16; kk++) {
            float4 a = *(const float4*)&Xs[kk][ty * 4];
            float4 b = *(const float4*)&Ws[kk][tx * 4];
            acc[0][0] = fmaf(a.x, b.x, acc[0][0]);
            acc[0][1] = fmaf(a.x, b.y, acc[0][1]);
            acc[0][2] = fmaf(a.x, b.z, acc[0][2]);
            acc[0][3] = fmaf(a.x, b.w, acc[0][3]);
            acc[1][0] = fmaf(a.y, b.x, acc[1][0]);
            acc[1][1] = fmaf(a.y, b.y, acc[1][1]);
            acc[1][2] = fmaf(a.y, b.z, acc[1][2]);
            acc[1][3] = fmaf(a.y, b.w, acc[1][3]);
            acc[2][0] = fmaf(a.z, b.x, acc[2][0]);
            acc[2][1] = fmaf(a.z, b.y, acc[2][1]);
            acc[2][2] = fmaf(a.z, b.z, acc[2][2]);
            acc[2][3] = fmaf(a.z, b.w, acc[2][3]);
            acc[3][0] = fmaf(a.w, b.x, acc[3][0]);
            acc[3][1] = fmaf(a.w, b.y, acc[3][1]);
            acc[3][2] = fmaf(a.w, b.z, acc[3][2]);
            acc[3][3] = fmaf(a.w, b.w, acc[3][3]);
        }
        __syncthreads();
    }

    const float4 bv = *(const float4*)&bias[n0 + tx * 4];
    if (split) {
        const int h = n0 >> 6;
        #pragma unroll
        for (int i = 0; i < 4; i++) {
            int mrow = m0 + ty * 4 + i;
            int b    = mrow >> 12;
            int srow = mrow & 4095;
            float4 r = make_float4(acc[i][0] + bv.x, acc[i][1] + bv.y,
                                   acc[i][2] + bv.z, acc[i][3] + bv.w);
            *(float4*)&out[(((size_t)(b * Hh + h)) * Ss + srow) * 64 + tx * 4] = r;
        }
    } else {
        #pragma unroll
        for (int i = 0; i < 4; i++) {
            int mrow = m0 + ty * 4 + i;
            float4 r = make_float4(acc[i][0] + bv.x, acc[i][1] + bv.y,
                                   acc[i][2] + bv.z, acc[i][3] + bv.w);
            *(float4*)&out[(size_t)mrow * Dd + n0 + tx * 4] = r;
        }
    }
}

// ---------------------------------------------------------------------------
// Causal flash attention with tf32 mma.sync (m16n8k8).
// Block: 128 threads (4 warps) per (64-row q-tile, b*h). Warp w owns q-rows
// [16w, 16w+16). Q lives as A-fragments in regs, O as C-fragments in regs,
// K/V tiles in smem (rows padded to 68 floats -> conflict-free B loads),
// P staged through warp-private smem rows (tf32-rounded).
// ---------------------------------------------------------------------------
#define PAD 68

__global__ __launch_bounds__(128) void attn_mma_kernel(const float* __restrict__ Qh,
                                                       const float* __restrict__ Kh,
                                                       const float* __restrict__ Vh,
                                                       float* __restrict__ feats)
{
    extern __shared__ float sm[];
    float (*Ks)[PAD] = (float(*)[PAD])sm;               // 64 x 68
    float (*Vs)[PAD] = (float(*)[PAD])(sm + 64 * PAD);  // 64 x 68
    float (*Ps)[PAD] = (float(*)[PAD])(sm + 128 * PAD); // 64 x 68 (also Q staging)

    const int qt   = gridDim.x - 1 - blockIdx.x;   // heavy tiles first
    const int bh   = blockIdx.y;
    const int tid  = threadIdx.x;
    const int w    = tid >> 5;
    const int lane = tid & 31;
    const int g    = lane >> 2;      // groupID
    const int t    = lane & 3;       // threadID_in_group
    const int r0   = w * 16 + g;     // local q-row (first)
    const int r1   = r0 + 8;         // local q-row (second)

    // ---- stage Q tile into Ps, then build persistent A-fragments (scaled, tf32)
    const float* qg = Qh + ((size_t)bh * Ss + (size_t)qt * 64) * 64;
    for (int i = tid; i < 1024; i += 128) {
        int row = i >> 4, c4 = (i & 15) * 4;
        float4 x = *(const float4*)(qg + row * 64 + c4);
        Ps[row][c4 + 0] = x.x; Ps[row][c4 + 1] = x.y;
        Ps[row][c4 + 2] = x.z; Ps[row][c4 + 3] = x.w;
    }
    __syncthreads();

    uint32_t qa[8][4];
    #pragma unroll
    for (int kk = 0; kk < 8; kk++) {
        qa[kk][0] = __float_as_uint(to_tf32(Ps[r0][kk*8 + t]     * 0.125f));
        qa[kk][1] = __float_as_uint(to_tf32(Ps[r1][kk*8 + t]     * 0.125f));
        qa[kk][2] = __float_as_uint(to_tf32(Ps[r0][kk*8 + t + 4] * 0.125f));
        qa[kk][3] = __float_as_uint(to_tf32(Ps[r1][kk*8 + t + 4] * 0.125f));
    }

    float o[8][4];
    #pragma unroll
    for (int n = 0; n < 8; n++) { o[n][0]=0.f; o[n][1]=0.f; o[n][2]=0.f; o[n][3]=0.f; }
    float m0 = -1e30f, m1 = -1e30f, l0 = 0.f, l1 = 0.f;

    const float* kg = Kh + (size_t)bh * Ss * 64;
    const float* vg = Vh + (size_t)bh * Ss * 64;

    for (int kt = 0; kt <= qt; kt++) {
        __syncthreads();   // prev iter's smem consumers done (also covers Q staging)

        const float* kp = kg + (size_t)kt * 64 * 64;
        const float* vp = vg + (size_t)kt * 64 * 64;
        for (int i = tid; i < 1024; i += 128) {
            int row = i >> 4, c4 = (i & 15) * 4;
            float4 kx = *(const float4*)(kp + row * 64 + c4);
            float4 vx = *(const float4*)(vp + row * 64 + c4);
            Ks[row][c4+0] = to_tf32(kx.x); Ks[row][c4+1] = to_tf32(kx.y);
            Ks[row][c4+2] = to_tf32(kx.z); Ks[row][c4+3] = to_tf32(kx.w);
            Vs[row][c4+0] = to_tf32(vx.x); Vs[row][c4+1] = to_tf32(vx.y);
            Vs[row][c4+2] = to_tf32(vx.z); Vs[row][c4+3] = to_tf32(vx.w);
        }
        __syncthreads();

        // ---- S = Q K^T  (C layout: c[n][0]=(r0,8n+2t) c[n][1]=(r0,8n+2t+1)
        //                            c[n][2]=(r1,8n+2t) c[n][3]=(r1,8n+2t+1))
        float c[8][4];
        #pragma unroll
        for (int n = 0; n < 8; n++) { c[n][0]=0.f; c[n][1]=0.f; c[n][2]=0.f; c[n][3]=0.f; }

        #pragma unroll
        for (int kk = 0; kk < 8; kk++) {
            #pragma unroll
            for (int n0 = 0; n0 < 8; n0++) {
                uint32_t b0 = __float_as_uint(Ks[n0*8 + g][kk*8 + t]);
                uint32_t b1 = __float_as_uint(Ks[n0*8 + g][kk*8 + t + 4]);
                mma_tf32(c[n0], qa[kk][0], qa[kk][1], qa[kk][2], qa[kk][3], b0, b1);
            }
        }

        if (kt == qt) {   // causal mask on diagonal tile (local indices, same offset)
            #pragma unroll
            for (int n0 = 0; n0 < 8; n0++) {
                int cb = n0*8 + 2*t;
                if (cb     > r0) c[n0][0] = -1e30f;
                if (cb + 1 > r0) c[n0][1] = -1e30f;
                if (cb     > r1) c[n0][2] = -1e30f;
                if (cb + 1 > r1) c[n0][3] = -1e30f;
            }
        }

        // ---- online softmax (per-row state; quad reduce over lanes t)
        float t0 = -1e30f, t1 = -1e30f;
        #pragma unroll
        for (int n0 = 0; n0 < 8; n0++) {
            t0 = fmaxf(t0, fmaxf(c[n0][0], c[n0][1]));
            t1 = fmaxf(t1, fmaxf(c[n0][2], c[n0][3]));
        }
        t0 = fmaxf(t0, __shfl_xor_sync(0xffffffffu, t0, 1));
        t0 = fmaxf(t0, __shfl_xor_sync(0xffffffffu, t0, 2));
        t1 = fmaxf(t1, __shfl_xor_sync(0xffffffffu, t1, 1));
        t1 = fmaxf(t1, __shfl_xor_sync(0xffffffffu, t1, 2));

        float mn0 = fmaxf(m0, t0), mn1 = fmaxf(m1, t1);
        float cor0 = __expf(m0 - mn0), cor1 = __expf(m1 - mn1);
        l0 *= cor0; l1 *= cor1;
        m0 = mn0;   m1 = mn1;
        #pragma unroll
        for (int n0 = 0; n0 < 8; n0++) {
            o[n0][0] *= cor0; o[n0][1] *= cor0;
            o[n0][2] *= cor1; o[n0][3] *= cor1;
        }

        // ---- P = exp(S - m), tf32-rounded, into warp-private smem rows
        #pragma unroll
        for (int n0 = 0; n0 < 8; n0++) {
            float p0 = to_tf32(__expf(c[n0][0] - mn0));
            float p1 = to_tf32(__expf(c[n0][1] - mn0));
            float p2 = to_tf32(__expf(c[n0][2] - mn1));
            float p3 = to_tf32(__expf(c[n0][3] - mn1));
            l0 += p0 + p1;
            l1 += p2 + p3;
            Ps[r0][n0*8 + 2*t]     = p0;
            Ps[r0][n0*8 + 2*t + 1] = p1;
            Ps[r1][n0*8 + 2*t]     = p2;
            Ps[r1][n0*8 + 2*t + 1] = p3;
        }
        __syncwarp();

        // ---- O += P V
        #pragma unroll
        for (int kk = 0; kk < 8; kk++) {
            uint32_t a0 = __float_as_uint(Ps[r0][kk*8 + t]);
            uint32_t a1 = __float_as_uint(Ps[r1][kk*8 + t]);
            uint32_t a2 = __float_as_uint(Ps[r0][kk*8 + t + 4]);
            uint32_t a3 = __float_as_uint(Ps[r1][kk*8 + t + 4]);
            #pragma unroll
            for (int n0 = 0; n0 < 8; n0++) {
                uint32_t b0 = __float_as_uint(Vs[kk*8 + t][n0*8 + g]);
                uint32_t b1 = __float_as_uint(Vs[kk*8 + t + 4][n0*8 + g]);
                mma_tf32(o[n0], a0, a1, a2, a3, b0, b1);
            }
        }
    }

    // ---- epilogue
    l0 += __shfl_xor_sync(0xffffffffu, l0, 1);
    l0 += __shfl_xor_sync(0xffffffffu, l0, 2);
    l1 += __shfl_xor_sync(0xffffffffu, l1, 1);
    l1 += __shfl_xor_sync(0xffffffffu, l1, 2);
    const float inv0 = 1.f / l0, inv1 = 1.f / l1;

    const int b = bh / Hh, h = bh - b * Hh;
    const int sq0 = qt * 64 + r0, sq1 = qt * 64 + r1;
    float* d0 = feats + ((size_t)b * Ss + sq0) * Dd + h * 64;
    float* d1 = feats + ((size_t)b * Ss + sq1) * Dd + h * 64;
    #pragma unroll
    for (int n0 = 0; n0 < 8; n0++) {
        *(float2*)(d0 + n0*8 + 2*t) = make_float2(o[n0][0] * inv0, o[n0][1] * inv0);
        *(float2*)(d1 + n0*8 + 2*t) = make_float2(o[n0][2] * inv1, o[n0][3] * inv1);
    }
}

// ---------------------------------------------------------------------------
extern "C" void kernel_launch(void* const* d_in, const int* in_sizes, int n_in,
                              void* d_out, int out_size)
{
    const float* q  = (const float*)d_in[0];
    const float* k  = (const float*)d_in[1];
    const float* v  = (const float*)d_in[2];
    // d_in[3] = mask (causal by construction; handled analytically)
    const float* Wq = (const float*)d_in[4];
    const float* bq = (const float*)d_in[5];
    const float* Wk = (const float*)d_in[6];
    const float* bk = (const float*)d_in[7];
    const float* Wv = (const float*)d_in[8];
    const float* bv = (const float*)d_in[9];
    const float* Wo = (const float*)d_in[10];
    const float* bo = (const float*)d_in[11];
    float* out = (float*)d_out;

    float *gq, *gk, *gv, *gf;
    cudaGetSymbolAddress((void**)&gq, g_Q);
    cudaGetSymbolAddress((void**)&gk, g_K);
    cudaGetSymbolAddress((void**)&gv, g_V);
    cudaGetSymbolAddress((void**)&gf, g_F);

    const int smem_attn = 3 * 64 * PAD * sizeof(float);   // 52224 B
    static int attr_set = 0;
    if (!attr_set) {
        cudaFuncSetAttribute(attn_mma_kernel,
                             cudaFuncAttributeMaxDynamicSharedMemorySize, smem_attn);
        attr_set = 1;
    }

    dim3 gg(Dd / 64, Mm / 64);        // (12, 128)
    gemm_kernel<<<gg, 256>>>(q, Wq, bq, gq, 1);
    gemm_kernel<<<gg, 256>>>(k, Wk, bk, gk, 1);
    gemm_kernel<<<gg, 256>>>(v, Wv, bv, gv, 1);

    attn_mma_kernel<<<dim3(Ss / 64, Bb * Hh), 128, smem_attn>>>(gq, gk, gv, gf);

    gemm_kernel<<<gg, 256>>>(gf, Wo, bo, out, 0);
}

// round 3
// speedup vs baseline: 3.2934x; 1.5204x over previous
#include <cuda_runtime.h>
#include <math.h>
#include <stdint.h>

#define Bb  2
#define Ss  4096
#define Dd  768
#define Hh  12
#define Mm  (Bb*Ss)   // 8192

// Scratch: head-split projections [B*H][S][64] and concat attention output [B,S,D]
__device__ float g_Q[(size_t)Bb*Hh*Ss*64];
__device__ float g_K[(size_t)Bb*Hh*Ss*64];
__device__ float g_V[(size_t)Bb*Hh*Ss*64];
__device__ float g_F[(size_t)Bb*Ss*Dd];

// ---------------------------------------------------------------------------
// helpers
// ---------------------------------------------------------------------------
__device__ __forceinline__ float to_tf32(float x) {
    uint32_t u;
    asm("cvt.rna.tf32.f32 %0, %1;" : "=r"(u) : "f"(x));
    return __uint_as_float(u);
}
__device__ __forceinline__ uint32_t fu(float x) { return __float_as_uint(x); }

__device__ __forceinline__ void mma_tf32(float c[4],
                                         uint32_t a0, uint32_t a1, uint32_t a2, uint32_t a3,
                                         uint32_t b0, uint32_t b1) {
    asm volatile(
        "mma.sync.aligned.m16n8k8.row.col.f32.tf32.tf32.f32 "
        "{%0,%1,%2,%3}, {%4,%5,%6,%7}, {%8,%9}, {%0,%1,%2,%3};\n"
        : "+f"(c[0]), "+f"(c[1]), "+f"(c[2]), "+f"(c[3])
        : "r"(a0), "r"(a1), "r"(a2), "r"(a3), "r"(b0), "r"(b1));
}

// ---------------------------------------------------------------------------
// tf32 tensor-core GEMM: C[M=8192, N=768] = X[M,768] @ W[768,768]^T + bias
// BM=128 BN=64 BK=16, 256 threads, warp grid 4m x 2n, warp tile 32x32.
// split=1: head-split layout; split=0: row-major
// ---------------------------------------------------------------------------
__global__ __launch_bounds__(256) void gemm_tf32(const float* __restrict__ X,
                                                 const float* __restrict__ W,
                                                 const float* __restrict__ bias,
                                                 float* __restrict__ out,
                                                 int split)
{
    __shared__ float Xs[128][20];   // pad 20: frag lane bank = (20g+t)%32 -> all distinct
    __shared__ float Ws[64][20];

    const int tid  = threadIdx.x;
    const int w    = tid >> 5;
    const int lane = tid & 31;
    const int g    = lane >> 2;
    const int t    = lane & 3;
    const int wm   = (w >> 1) * 32;   // warp m offset in tile
    const int wn   = (w & 1) * 32;    // warp n offset in tile
    const int n0   = blockIdx.x * 64;
    const int m0   = blockIdx.y * 128;

    // loaders: X 128 rows x 16 cols (2 float4/thread), W 64 rows x 16 cols (1 float4/thread)
    const int xr = tid >> 1;             // 0..127
    const int xc = (tid & 1) * 8;        // 0 or 8
    const int wr = tid >> 2;             // 0..63
    const int wc = (tid & 3) * 4;        // 0,4,8,12

    const float* xp = X + (size_t)(m0 + xr) * Dd + xc;
    const float* wp = W + (size_t)(n0 + wr) * Dd + wc;

    float c[2][4][4];
    #pragma unroll
    for (int mt = 0; mt < 2; mt++)
        #pragma unroll
        for (int nt = 0; nt < 4; nt++)
            { c[mt][nt][0]=0.f; c[mt][nt][1]=0.f; c[mt][nt][2]=0.f; c[mt][nt][3]=0.f; }

    float4 px0 = *(const float4*)(xp);
    float4 px1 = *(const float4*)(xp + 4);
    float4 pwv = *(const float4*)(wp);

    for (int k0 = 0; k0 < Dd; k0 += 16) {
        if (k0) __syncthreads();
        *(float4*)&Xs[xr][xc]     = make_float4(to_tf32(px0.x), to_tf32(px0.y),
                                                to_tf32(px0.z), to_tf32(px0.w));
        *(float4*)&Xs[xr][xc + 4] = make_float4(to_tf32(px1.x), to_tf32(px1.y),
                                                to_tf32(px1.z), to_tf32(px1.w));
        *(float4*)&Ws[wr][wc]     = make_float4(to_tf32(pwv.x), to_tf32(pwv.y),
                                                to_tf32(pwv.z), to_tf32(pwv.w));
        __syncthreads();

        if (k0 + 16 < Dd) {
            px0 = *(const float4*)(xp + k0 + 16);
            px1 = *(const float4*)(xp + k0 + 20);
            pwv = *(const float4*)(wp + k0 + 16);
        }

        #pragma unroll
        for (int kk = 0; kk < 16; kk += 8) {
            uint32_t a[2][4];
            #pragma unroll
            for (int mt = 0; mt < 2; mt++) {
                const int mb = wm + mt * 16;
                a[mt][0] = fu(Xs[mb + g][kk + t]);
                a[mt][1] = fu(Xs[mb + 8 + g][kk + t]);
                a[mt][2] = fu(Xs[mb + g][kk + t + 4]);
                a[mt][3] = fu(Xs[mb + 8 + g][kk + t + 4]);
            }
            #pragma unroll
            for (int nt = 0; nt < 4; nt++) {
                uint32_t b0 = fu(Ws[wn + nt * 8 + g][kk + t]);
                uint32_t b1 = fu(Ws[wn + nt * 8 + g][kk + t + 4]);
                mma_tf32(c[0][nt], a[0][0], a[0][1], a[0][2], a[0][3], b0, b1);
                mma_tf32(c[1][nt], a[1][0], a[1][1], a[1][2], a[1][3], b0, b1);
            }
        }
    }

    // epilogue
    const int h = n0 >> 6;   // split=1: whole 64-col tile is one head
    #pragma unroll
    for (int mt = 0; mt < 2; mt++) {
        const int ra = m0 + wm + mt * 16 + g;
        const int rb = ra + 8;
        #pragma unroll
        for (int nt = 0; nt < 4; nt++) {
            const int coln = wn + nt * 8 + 2 * t;           // col within 64-tile
            const float2 bv = *(const float2*)&bias[n0 + coln];
            float2 va = make_float2(c[mt][nt][0] + bv.x, c[mt][nt][1] + bv.y);
            float2 vb = make_float2(c[mt][nt][2] + bv.x, c[mt][nt][3] + bv.y);
            if (split) {
                int ba = ra >> 12, sa = ra & 4095;
                int bb = rb >> 12, sb = rb & 4095;
                *(float2*)&out[(((size_t)(ba * Hh + h)) * Ss + sa) * 64 + coln] = va;
                *(float2*)&out[(((size_t)(bb * Hh + h)) * Ss + sb) * 64 + coln] = vb;
            } else {
                *(float2*)&out[(size_t)ra * Dd + n0 + coln] = va;
                *(float2*)&out[(size_t)rb * Dd + n0 + coln] = vb;
            }
        }
    }
}

// ---------------------------------------------------------------------------
// Causal flash attention with tf32 mma.sync (m16n8k8). (unchanged from R2)
// ---------------------------------------------------------------------------
#define PAD 68

__global__ __launch_bounds__(128) void attn_mma_kernel(const float* __restrict__ Qh,
                                                       const float* __restrict__ Kh,
                                                       const float* __restrict__ Vh,
                                                       float* __restrict__ feats)
{
    extern __shared__ float sm[];
    float (*Ks)[PAD] = (float(*)[PAD])sm;               // 64 x 68
    float (*Vs)[PAD] = (float(*)[PAD])(sm + 64 * PAD);  // 64 x 68
    float (*Ps)[PAD] = (float(*)[PAD])(sm + 128 * PAD); // 64 x 68 (also Q staging)

    const int qt   = gridDim.x - 1 - blockIdx.x;   // heavy tiles first
    const int bh   = blockIdx.y;
    const int tid  = threadIdx.x;
    const int w    = tid >> 5;
    const int lane = tid & 31;
    const int g    = lane >> 2;
    const int t    = lane & 3;
    const int r0   = w * 16 + g;
    const int r1   = r0 + 8;

    const float* qg = Qh + ((size_t)bh * Ss + (size_t)qt * 64) * 64;
    for (int i = tid; i < 1024; i += 128) {
        int row = i >> 4, c4 = (i & 15) * 4;
        float4 x = *(const float4*)(qg + row * 64 + c4);
        Ps[row][c4 + 0] = x.x; Ps[row][c4 + 1] = x.y;
        Ps[row][c4 + 2] = x.z; Ps[row][c4 + 3] = x.w;
    }
    __syncthreads();

    uint32_t qa[8][4];
    #pragma unroll
    for (int kk = 0; kk < 8; kk++) {
        qa[kk][0] = fu(to_tf32(Ps[r0][kk*8 + t]     * 0.125f));
        qa[kk][1] = fu(to_tf32(Ps[r1][kk*8 + t]     * 0.125f));
        qa[kk][2] = fu(to_tf32(Ps[r0][kk*8 + t + 4] * 0.125f));
        qa[kk][3] = fu(to_tf32(Ps[r1][kk*8 + t + 4] * 0.125f));
    }

    float o[8][4];
    #pragma unroll
    for (int n = 0; n < 8; n++) { o[n][0]=0.f; o[n][1]=0.f; o[n][2]=0.f; o[n][3]=0.f; }
    float m0 = -1e30f, m1 = -1e30f, l0 = 0.f, l1 = 0.f;

    const float* kg = Kh + (size_t)bh * Ss * 64;
    const float* vg = Vh + (size_t)bh * Ss * 64;

    for (int kt = 0; kt <= qt; kt++) {
        __syncthreads();

        const float* kp = kg + (size_t)kt * 64 * 64;
        const float* vp = vg + (size_t)kt * 64 * 64;
        for (int i = tid; i < 1024; i += 128) {
            int row = i >> 4, c4 = (i & 15) * 4;
            float4 kx = *(const float4*)(kp + row * 64 + c4);
            float4 vx = *(const float4*)(vp + row * 64 + c4);
            Ks[row][c4+0] = to_tf32(kx.x); Ks[row][c4+1] = to_tf32(kx.y);
            Ks[row][c4+2] = to_tf32(kx.z); Ks[row][c4+3] = to_tf32(kx.w);
            Vs[row][c4+0] = to_tf32(vx.x); Vs[row][c4+1] = to_tf32(vx.y);
            Vs[row][c4+2] = to_tf32(vx.z); Vs[row][c4+3] = to_tf32(vx.w);
        }
        __syncthreads();

        float c[8][4];
        #pragma unroll
        for (int n = 0; n < 8; n++) { c[n][0]=0.f; c[n][1]=0.f; c[n][2]=0.f; c[n][3]=0.f; }

        #pragma unroll
        for (int kk = 0; kk < 8; kk++) {
            #pragma unroll
            for (int n0 = 0; n0 < 8; n0++) {
                uint32_t b0 = fu(Ks[n0*8 + g][kk*8 + t]);
                uint32_t b1 = fu(Ks[n0*8 + g][kk*8 + t + 4]);
                mma_tf32(c[n0], qa[kk][0], qa[kk][1], qa[kk][2], qa[kk][3], b0, b1);
            }
        }

        if (kt == qt) {
            #pragma unroll
            for (int n0 = 0; n0 < 8; n0++) {
                int cb = n0*8 + 2*t;
                if (cb     > r0) c[n0][0] = -1e30f;
                if (cb + 1 > r0) c[n0][1] = -1e30f;
                if (cb     > r1) c[n0][2] = -1e30f;
                if (cb + 1 > r1) c[n0][3] = -1e30f;
            }
        }

        float t0 = -1e30f, t1 = -1e30f;
        #pragma unroll
        for (int n0 = 0; n0 < 8; n0++) {
            t0 = fmaxf(t0, fmaxf(c[n0][0], c[n0][1]));
            t1 = fmaxf(t1, fmaxf(c[n0][2], c[n0][3]));
        }
        t0 = fmaxf(t0, __shfl_xor_sync(0xffffffffu, t0, 1));
        t0 = fmaxf(t0, __shfl_xor_sync(0xffffffffu, t0, 2));
        t1 = fmaxf(t1, __shfl_xor_sync(0xffffffffu, t1, 1));
        t1 = fmaxf(t1, __shfl_xor_sync(0xffffffffu, t1, 2));

        float mn0 = fmaxf(m0, t0), mn1 = fmaxf(m1, t1);
        float cor0 = __expf(m0 - mn0), cor1 = __expf(m1 - mn1);
        l0 *= cor0; l1 *= cor1;
        m0 = mn0;   m1 = mn1;
        #pragma unroll
        for (int n0 = 0; n0 < 8; n0++) {
            o[n0][0] *= cor0; o[n0][1] *= cor0;
            o[n0][2] *= cor1; o[n0][3] *= cor1;
        }

        #pragma unroll
        for (int n0 = 0; n0 < 8; n0++) {
            float p0 = to_tf32(__expf(c[n0][0] - mn0));
            float p1 = to_tf32(__expf(c[n0][1] - mn0));
            float p2 = to_tf32(__expf(c[n0][2] - mn1));
            float p3 = to_tf32(__expf(c[n0][3] - mn1));
            l0 += p0 + p1;
            l1 += p2 + p3;
            Ps[r0][n0*8 + 2*t]     = p0;
            Ps[r0][n0*8 + 2*t + 1] = p1;
            Ps[r1][n0*8 + 2*t]     = p2;
            Ps[r1][n0*8 + 2*t + 1] = p3;
        }
        __syncwarp();

        #pragma unroll
        for (int kk = 0; kk < 8; kk++) {
            uint32_t a0 = fu(Ps[r0][kk*8 + t]);
            uint32_t a1 = fu(Ps[r1][kk*8 + t]);
            uint32_t a2 = fu(Ps[r0][kk*8 + t + 4]);
            uint32_t a3 = fu(Ps[r1][kk*8 + t + 4]);
            #pragma unroll
            for (int n0 = 0; n0 < 8; n0++) {
                uint32_t b0 = fu(Vs[kk*8 + t][n0*8 + g]);
                uint32_t b1 = fu(Vs[kk*8 + t + 4][n0*8 + g]);
                mma_tf32(o[n0], a0, a1, a2, a3, b0, b1);
            }
        }
    }

    l0 += __shfl_xor_sync(0xffffffffu, l0, 1);
    l0 += __shfl_xor_sync(0xffffffffu, l0, 2);
    l1 += __shfl_xor_sync(0xffffffffu, l1, 1);
    l1 += __shfl_xor_sync(0xffffffffu, l1, 2);
    const float inv0 = 1.f / l0, inv1 = 1.f / l1;

    const int b = bh / Hh, h = bh - b * Hh;
    const int sq0 = qt * 64 + r0, sq1 = qt * 64 + r1;
    float* d0 = feats + ((size_t)b * Ss + sq0) * Dd + h * 64;
    float* d1 = feats + ((size_t)b * Ss + sq1) * Dd + h * 64;
    #pragma unroll
    for (int n0 = 0; n0 < 8; n0++) {
        *(float2*)(d0 + n0*8 + 2*t) = make_float2(o[n0][0] * inv0, o[n0][1] * inv0);
        *(float2*)(d1 + n0*8 + 2*t) = make_float2(o[n0][2] * inv1, o[n0][3] * inv1);
    }
}

// ---------------------------------------------------------------------------
extern "C" void kernel_launch(void* const* d_in, const int* in_sizes, int n_in,
                              void* d_out, int out_size)
{
    const float* q  = (const float*)d_in[0];
    const float* k  = (const float*)d_in[1];
    const float* v  = (const float*)d_in[2];
    // d_in[3] = mask (causal by construction; handled analytically)
    const float* Wq = (const float*)d_in[4];
    const float* bq = (const float*)d_in[5];
    const float* Wk = (const float*)d_in[6];
    const float* bk = (const float*)d_in[7];
    const float* Wv = (const float*)d_in[8];
    const float* bv = (const float*)d_in[9];
    const float* Wo = (const float*)d_in[10];
    const float* bo = (const float*)d_in[11];
    float* out = (float*)d_out;

    float *gq, *gk, *gv, *gf;
    cudaGetSymbolAddress((void**)&gq, g_Q);
    cudaGetSymbolAddress((void**)&gk, g_K);
    cudaGetSymbolAddress((void**)&gv, g_V);
    cudaGetSymbolAddress((void**)&gf, g_F);

    const int smem_attn = 3 * 64 * PAD * sizeof(float);   // 52224 B
    static int attr_set = 0;
    if (!attr_set) {
        cudaFuncSetAttribute(attn_mma_kernel,
                             cudaFuncAttributeMaxDynamicSharedMemorySize, smem_attn);
        attr_set = 1;
    }

    dim3 gg(Dd / 64, Mm / 128);       // (12, 64)
    gemm_tf32<<<gg, 256>>>(q, Wq, bq, gq, 1);
    gemm_tf32<<<gg, 256>>>(k, Wk, bk, gk, 1);
    gemm_tf32<<<gg, 256>>>(v, Wv, bv, gv, 1);

    attn_mma_kernel<<<dim3(Ss / 64, Bb * Hh), 128, smem_attn>>>(gq, gk, gv, gf);

    gemm_tf32<<<gg, 256>>>(gf, Wo, bo, out, 0);
}

// round 4
// speedup vs baseline: 3.4526x; 1.0483x over previous
#include <cuda_runtime.h>
#include <math.h>
#include <stdint.h>

#define Bb  2
#define Ss  4096
#define Dd  768
#define Hh  12
#define Mm  (Bb*Ss)   // 8192

// Scratch.
// g_Q : head-split row-major [bh][s][64]
// g_KF/g_VF : fragment-packed [bh][kt][8 n0][4 kkp][32 lane][4 comp]
// g_F : attention output [B,S,D]
// g_WF: fragment-packed weights [4][96 n0][48 kkp][32 lane][4 comp]
__device__ float g_Q [(size_t)Bb*Hh*Ss*64];
__device__ float g_KF[(size_t)Bb*Hh*Ss*64];
__device__ float g_VF[(size_t)Bb*Hh*Ss*64];
__device__ float g_F [(size_t)Bb*Ss*Dd];
__device__ float g_WF[(size_t)4*Dd*Dd];

// ---------------------------------------------------------------------------
__device__ __forceinline__ float to_tf32(float x) {
    uint32_t u;
    asm("cvt.rna.tf32.f32 %0, %1;" : "=r"(u) : "f"(x));
    return __uint_as_float(u);
}
__device__ __forceinline__ uint32_t fu(float x) { return __float_as_uint(x); }

__device__ __forceinline__ void mma_tf32(float c[4],
                                         uint32_t a0, uint32_t a1, uint32_t a2, uint32_t a3,
                                         uint32_t b0, uint32_t b1) {
    asm volatile(
        "mma.sync.aligned.m16n8k8.row.col.f32.tf32.tf32.f32 "
        "{%0,%1,%2,%3}, {%4,%5,%6,%7}, {%8,%9}, {%0,%1,%2,%3};\n"
        : "+f"(c[0]), "+f"(c[1]), "+f"(c[2]), "+f"(c[3])
        : "r"(a0), "r"(a1), "r"(a2), "r"(a3), "r"(b0), "r"(b1));
}

// ---------------------------------------------------------------------------
// W pre-pack: W[768][768] row-major -> fragment-packed + tf32-rounded.
// value W[n][k]: n0=n/8, g=n%8, kkp=k/16, t=(k%16)%4, comp=(k%16)/4
// addr = ((n0*48+kkp)*32 + g*4+t)*4 + comp
// ---------------------------------------------------------------------------
__global__ __launch_bounds__(256) void pack_w(const float* __restrict__ W0,
                                              const float* __restrict__ W1,
                                              const float* __restrict__ W2,
                                              const float* __restrict__ W3,
                                              float* __restrict__ out)
{
    const float* W = (blockIdx.y == 0) ? W0 : (blockIdx.y == 1) ? W1
                   : (blockIdx.y == 2) ? W2 : W3;
    float* o = out + (size_t)blockIdx.y * Dd * Dd;

    int idx = blockIdx.x * 256 + threadIdx.x;   // 0..147455
    int n   = idx / 192;
    int k4  = (idx % 192) * 4;
    float4 v = *(const float4*)&W[(size_t)n * Dd + k4];
    int n0 = n >> 3, g = n & 7;
    int kkp = k4 >> 4, r = k4 & 15, comp = r >> 2;   // t runs 0..3 over components
    float* base = o + ((size_t)(n0 * 48 + kkp) * 32 + g * 4) * 4 + comp;
    base[0]  = to_tf32(v.x);
    base[4]  = to_tf32(v.y);
    base[8]  = to_tf32(v.z);
    base[12] = to_tf32(v.w);
}

// ---------------------------------------------------------------------------
// tf32 GEMM: C[M,768] = X[M,768] @ W^T + bias.  W pre-packed (WF).
// BM=128 BN=64 BK=16, 256 thr, warps 4m x 2n, warp tile 32x32.
// mode: 0 = row-major fp32 (final out)
//       1 = head-split row-major (Q)
//       2 = fragment-packed K layout (+tf32 round)
//       3 = fragment-packed V layout (+tf32 round)
// ---------------------------------------------------------------------------
__global__ __launch_bounds__(256) void gemm2(const float* __restrict__ X,
                                             const float* __restrict__ WF,
                                             const float* __restrict__ bias,
                                             float* __restrict__ out,
                                             int mode)
{
    __shared__ float Xs[128][20];   // pad 20: frag lane bank = (20g+t)%32 distinct

    const int tid  = threadIdx.x;
    const int w    = tid >> 5;
    const int lane = tid & 31;
    const int g    = lane >> 2;
    const int t    = lane & 3;
    const int wm   = (w >> 1) * 32;
    const int wn   = (w & 1) * 32;
    const int n0   = blockIdx.x * 64;
    const int m0   = blockIdx.y * 128;

    const int xr = tid >> 1;
    const int xc = (tid & 1) * 8;
    const float* xp = X + (size_t)(m0 + xr) * Dd + xc;

    const size_t nb0 = (size_t)blockIdx.x * 8 + (wn >> 3);   // global n-block of nt=0

    float c[2][4][4];
    #pragma unroll
    for (int mt = 0; mt < 2; mt++)
        #pragma unroll
        for (int nt = 0; nt < 4; nt++)
            { c[mt][nt][0]=0.f; c[mt][nt][1]=0.f; c[mt][nt][2]=0.f; c[mt][nt][3]=0.f; }

    float4 px0 = *(const float4*)(xp);
    float4 px1 = *(const float4*)(xp + 4);
    float4 bpre[4];
    #pragma unroll
    for (int nt = 0; nt < 4; nt++)
        bpre[nt] = *(const float4*)&WF[(((nb0 + nt) * 48) * 32 + lane) * 4];

    for (int k0 = 0; k0 < Dd; k0 += 16) {
        if (k0) __syncthreads();
        *(float4*)&Xs[xr][xc]     = make_float4(to_tf32(px0.x), to_tf32(px0.y),
                                                to_tf32(px0.z), to_tf32(px0.w));
        *(float4*)&Xs[xr][xc + 4] = make_float4(to_tf32(px1.x), to_tf32(px1.y),
                                                to_tf32(px1.z), to_tf32(px1.w));
        __syncthreads();

        float4 bcur[4];
        #pragma unroll
        for (int nt = 0; nt < 4; nt++) bcur[nt] = bpre[nt];

        if (k0 + 16 < Dd) {
            px0 = *(const float4*)(xp + k0 + 16);
            px1 = *(const float4*)(xp + k0 + 20);
            const int kkp_n = (k0 >> 4) + 1;
            #pragma unroll
            for (int nt = 0; nt < 4; nt++)
                bpre[nt] = *(const float4*)&WF[(((nb0 + nt) * 48 + kkp_n) * 32 + lane) * 4];
        }

        #pragma unroll
        for (int kk2 = 0; kk2 < 2; kk2++) {
            const int kk = kk2 * 8;
            uint32_t a[2][4];
            #pragma unroll
            for (int mt = 0; mt < 2; mt++) {
                const int mb = wm + mt * 16;
                a[mt][0] = fu(Xs[mb + g][kk + t]);
                a[mt][1] = fu(Xs[mb + 8 + g][kk + t]);
                a[mt][2] = fu(Xs[mb + g][kk + t + 4]);
                a[mt][3] = fu(Xs[mb + 8 + g][kk + t + 4]);
            }
            #pragma unroll
            for (int nt = 0; nt < 4; nt++) {
                uint32_t b0 = kk2 ? fu(bcur[nt].z) : fu(bcur[nt].x);
                uint32_t b1 = kk2 ? fu(bcur[nt].w) : fu(bcur[nt].y);
                mma_tf32(c[0][nt], a[0][0], a[0][1], a[0][2], a[0][3], b0, b1);
                mma_tf32(c[1][nt], a[1][0], a[1][1], a[1][2], a[1][3], b0, b1);
            }
        }
    }

    // ---- epilogue
    const int h = blockIdx.x;   // split modes: 64-col tile == one head
    #pragma unroll
    for (int mt = 0; mt < 2; mt++) {
        const int ra = m0 + wm + mt * 16 + g;
        const int rb = ra + 8;
        #pragma unroll
        for (int nt = 0; nt < 4; nt++) {
            const int coln = wn + nt * 8 + 2 * t;
            const float2 bv = *(const float2*)&bias[n0 + coln];
            float vax = c[mt][nt][0] + bv.x, vay = c[mt][nt][1] + bv.y;
            float vbx = c[mt][nt][2] + bv.x, vby = c[mt][nt][3] + bv.y;

            if (mode == 0) {
                *(float2*)&out[(size_t)ra * Dd + n0 + coln] = make_float2(vax, vay);
                *(float2*)&out[(size_t)rb * Dd + n0 + coln] = make_float2(vbx, vby);
            } else if (mode == 1) {
                int ba = ra >> 12, sa = ra & 4095;
                int bb = rb >> 12, sb = rb & 4095;
                *(float2*)&out[(((size_t)(ba * Hh + h)) * Ss + sa) * 64 + coln] = make_float2(vax, vay);
                *(float2*)&out[(((size_t)(bb * Hh + h)) * Ss + sb) * 64 + coln] = make_float2(vbx, vby);
            } else if (mode == 2) {
                // K fragment layout: row=seq -> (n0f,gg); col=dim -> (kkp,tt,comp)
                const int kkp = coln >> 4, rr = coln & 15, tt = rr & 3, cp = rr >> 2;
                #pragma unroll
                for (int e = 0; e < 2; e++) {
                    int row = e ? rb : ra;
                    float v0 = e ? vbx : vax, v1 = e ? vby : vay;
                    int bB = row >> 12, s = row & 4095;
                    int kt = s >> 6, sl = s & 63, nn = sl >> 3, gg = sl & 7;
                    size_t base = ((size_t)(bB * Hh + h)) * Ss * 64 + (size_t)kt * 4096
                                + ((size_t)(nn * 4 + kkp) * 32 + gg * 4 + tt) * 4 + cp;
                    out[base]     = to_tf32(v0);
                    out[base + 4] = to_tf32(v1);   // tt+1
                }
            } else {
                // V fragment layout: row=seq -> (kkp,tt,comp); col=dim -> (nn,gg)
                const int nn = coln >> 3, gg = coln & 7;
                #pragma unroll
                for (int e = 0; e < 2; e++) {
                    int row = e ? rb : ra;
                    float v0 = e ? vbx : vax, v1 = e ? vby : vay;
                    int bB = row >> 12, s = row & 4095;
                    int kt = s >> 6, sl = s & 63;
                    int kkp = sl >> 4, rr = sl & 15, tt = rr & 3, cp = rr >> 2;
                    size_t base = ((size_t)(bB * Hh + h)) * Ss * 64 + (size_t)kt * 4096
                                + ((size_t)(nn * 4 + kkp) * 32 + gg * 4 + tt) * 4 + cp;
                    out[base]      = to_tf32(v0);
                    out[base + 16] = to_tf32(v1);   // gg+1 -> +4 lane-slots
                }
            }
        }
    }
}

// ---------------------------------------------------------------------------
// Causal flash attention, tf32 mma, fragment-packed K/V tiles.
// Block: 128 thr (4 warps) per (64-row q-tile, b*h); warp owns 16 q-rows.
// ---------------------------------------------------------------------------
__global__ __launch_bounds__(128) void attn_mma2(const float* __restrict__ Qh,
                                                 const float* __restrict__ KF,
                                                 const float* __restrict__ VF,
                                                 float* __restrict__ feats)
{
    extern __shared__ float sm[];
    float* Ks = sm;            // 4096 floats, fragment-packed tile
    float* Vs = sm + 4096;     // 4096
    float (*Ps)[68] = (float(*)[68])(sm + 8192);   // 64 x 68 (Q stage + P)

    const int qt   = gridDim.x - 1 - blockIdx.x;   // heavy tiles first
    const int bh   = blockIdx.y;
    const int tid  = threadIdx.x;
    const int w    = tid >> 5;
    const int lane = tid & 31;
    const int g    = lane >> 2;
    const int t    = lane & 3;
    const int r0   = w * 16 + g;
    const int r1   = r0 + 8;

    // ---- stage Q, build persistent scaled A-fragments
    const float* qg = Qh + ((size_t)bh * Ss + (size_t)qt * 64) * 64;
    for (int i = tid; i < 1024; i += 128) {
        int row = i >> 4, c4 = (i & 15) * 4;
        float4 x = *(const float4*)(qg + row * 64 + c4);
        Ps[row][c4 + 0] = x.x; Ps[row][c4 + 1] = x.y;
        Ps[row][c4 + 2] = x.z; Ps[row][c4 + 3] = x.w;
    }
    __syncthreads();

    uint32_t qa[8][4];
    #pragma unroll
    for (int kk = 0; kk < 8; kk++) {
        qa[kk][0] = fu(to_tf32(Ps[r0][kk*8 + t]     * 0.125f));
        qa[kk][1] = fu(to_tf32(Ps[r1][kk*8 + t]     * 0.125f));
        qa[kk][2] = fu(to_tf32(Ps[r0][kk*8 + t + 4] * 0.125f));
        qa[kk][3] = fu(to_tf32(Ps[r1][kk*8 + t + 4] * 0.125f));
    }

    float o[8][4];
    #pragma unroll
    for (int n = 0; n < 8; n++) { o[n][0]=0.f; o[n][1]=0.f; o[n][2]=0.f; o[n][3]=0.f; }
    float m0 = -1e30f, m1 = -1e30f, l0 = 0.f, l1 = 0.f;

    const float* kg = KF + (size_t)bh * Ss * 64;
    const float* vg = VF + (size_t)bh * Ss * 64;

    for (int kt = 0; kt <= qt; kt++) {
        __syncthreads();
        const float4* kp = (const float4*)(kg + (size_t)kt * 4096);
        const float4* vp = (const float4*)(vg + (size_t)kt * 4096);
        float4* KsV = (float4*)Ks;
        float4* VsV = (float4*)Vs;
        #pragma unroll
        for (int i = 0; i < 8; i++) {           // contiguous coalesced copies
            KsV[tid + 128*i] = kp[tid + 128*i];
            VsV[tid + 128*i] = vp[tid + 128*i];
        }
        __syncthreads();

        // ---- S = Q K^T
        float c[8][4];
        #pragma unroll
        for (int n = 0; n < 8; n++) { c[n][0]=0.f; c[n][1]=0.f; c[n][2]=0.f; c[n][3]=0.f; }

        #pragma unroll
        for (int kkp = 0; kkp < 4; kkp++) {
            #pragma unroll
            for (int n0 = 0; n0 < 8; n0++) {
                float4 bf = *(const float4*)&Ks[((n0*4 + kkp)*32 + lane)*4];
                mma_tf32(c[n0], qa[2*kkp][0],   qa[2*kkp][1],   qa[2*kkp][2],   qa[2*kkp][3],
                         fu(bf.x), fu(bf.y));
                mma_tf32(c[n0], qa[2*kkp+1][0], qa[2*kkp+1][1], qa[2*kkp+1][2], qa[2*kkp+1][3],
                         fu(bf.z), fu(bf.w));
            }
        }

        if (kt == qt) {   // causal mask on diagonal tile
            #pragma unroll
            for (int n0 = 0; n0 < 8; n0++) {
                int cb = n0*8 + 2*t;
                if (cb     > r0) c[n0][0] = -1e30f;
                if (cb + 1 > r0) c[n0][1] = -1e30f;
                if (cb     > r1) c[n0][2] = -1e30f;
                if (cb + 1 > r1) c[n0][3] = -1e30f;
            }
        }

        // ---- online softmax
        float t0 = -1e30f, t1 = -1e30f;
        #pragma unroll
        for (int n0 = 0; n0 < 8; n0++) {
            t0 = fmaxf(t0, fmaxf(c[n0][0], c[n0][1]));
            t1 = fmaxf(t1, fmaxf(c[n0][2], c[n0][3]));
        }
        t0 = fmaxf(t0, __shfl_xor_sync(0xffffffffu, t0, 1));
        t0 = fmaxf(t0, __shfl_xor_sync(0xffffffffu, t0, 2));
        t1 = fmaxf(t1, __shfl_xor_sync(0xffffffffu, t1, 1));
        t1 = fmaxf(t1, __shfl_xor_sync(0xffffffffu, t1, 2));

        float mn0 = fmaxf(m0, t0), mn1 = fmaxf(m1, t1);
        float cor0 = __expf(m0 - mn0), cor1 = __expf(m1 - mn1);
        l0 *= cor0; l1 *= cor1;
        m0 = mn0;   m1 = mn1;
        #pragma unroll
        for (int n0 = 0; n0 < 8; n0++) {
            o[n0][0] *= cor0; o[n0][1] *= cor0;
            o[n0][2] *= cor1; o[n0][3] *= cor1;
        }

        #pragma unroll
        for (int n0 = 0; n0 < 8; n0++) {
            float p0 = to_tf32(__expf(c[n0][0] - mn0));
            float p1 = to_tf32(__expf(c[n0][1] - mn0));
            float p2 = to_tf32(__expf(c[n0][2] - mn1));
            float p3 = to_tf32(__expf(c[n0][3] - mn1));
            l0 += p0 + p1;
            l1 += p2 + p3;
            Ps[r0][n0*8 + 2*t]     = p0;
            Ps[r0][n0*8 + 2*t + 1] = p1;
            Ps[r1][n0*8 + 2*t]     = p2;
            Ps[r1][n0*8 + 2*t + 1] = p3;
        }
        __syncwarp();

        // ---- O += P V
        #pragma unroll
        for (int kkp = 0; kkp < 4; kkp++) {
            uint32_t pa[2][4];
            #pragma unroll
            for (int q2 = 0; q2 < 2; q2++) {
                int kk = 2*kkp + q2;
                pa[q2][0] = fu(Ps[r0][kk*8 + t]);
                pa[q2][1] = fu(Ps[r1][kk*8 + t]);
                pa[q2][2] = fu(Ps[r0][kk*8 + t + 4]);
                pa[q2][3] = fu(Ps[r1][kk*8 + t + 4]);
            }
            #pragma unroll
            for (int n0 = 0; n0 < 8; n0++) {
                float4 bf = *(const float4*)&Vs[((n0*4 + kkp)*32 + lane)*4];
                mma_tf32(o[n0], pa[0][0], pa[0][1], pa[0][2], pa[0][3], fu(bf.x), fu(bf.y));
                mma_tf32(o[n0], pa[1][0], pa[1][1], pa[1][2], pa[1][3], fu(bf.z), fu(bf.w));
            }
        }
    }

    // ---- epilogue
    l0 += __shfl_xor_sync(0xffffffffu, l0, 1);
    l0 += __shfl_xor_sync(0xffffffffu, l0, 2);
    l1 += __shfl_xor_sync(0xffffffffu, l1, 1);
    l1 += __shfl_xor_sync(0xffffffffu, l1, 2);
    const float inv0 = 1.f / l0, inv1 = 1.f / l1;

    const int b = bh / Hh, h = bh - b * Hh;
    const int sq0 = qt * 64 + r0, sq1 = qt * 64 + r1;
    float* d0 = feats + ((size_t)b * Ss + sq0) * Dd + h * 64;
    float* d1 = feats + ((size_t)b * Ss + sq1) * Dd + h * 64;
    #pragma unroll
    for (int n0 = 0; n0 < 8; n0++) {
        *(float2*)(d0 + n0*8 + 2*t) = make_float2(o[n0][0] * inv0, o[n0][1] * inv0);
        *(float2*)(d1 + n0*8 + 2*t) = make_float2(o[n0][2] * inv1, o[n0][3] * inv1);
    }
}

// ---------------------------------------------------------------------------
extern "C" void kernel_launch(void* const* d_in, const int* in_sizes, int n_in,
                              void* d_out, int out_size)
{
    const float* q  = (const float*)d_in[0];
    const float* k  = (const float*)d_in[1];
    const float* v  = (const float*)d_in[2];
    // d_in[3] = mask (causal by construction; handled analytically)
    const float* Wq = (const float*)d_in[4];
    const float* bq = (const float*)d_in[5];
    const float* Wk = (const float*)d_in[6];
    const float* bk = (const float*)d_in[7];
    const float* Wv = (const float*)d_in[8];
    const float* bv = (const float*)d_in[9];
    const float* Wo = (const float*)d_in[10];
    const float* bo = (const float*)d_in[11];
    float* out = (float*)d_out;

    float *gq, *gkf, *gvf, *gf, *gwf;
    cudaGetSymbolAddress((void**)&gq,  g_Q);
    cudaGetSymbolAddress((void**)&gkf, g_KF);
    cudaGetSymbolAddress((void**)&gvf, g_VF);
    cudaGetSymbolAddress((void**)&gf,  g_F);
    cudaGetSymbolAddress((void**)&gwf, g_WF);

    const int smem_attn = (4096 + 4096 + 64*68) * sizeof(float);   // 50176 B
    static int attr_set = 0;
    if (!attr_set) {
        cudaFuncSetAttribute(attn_mma2,
                             cudaFuncAttributeMaxDynamicSharedMemorySize, smem_attn);
        attr_set = 1;
    }

    pack_w<<<dim3(576, 4), 256>>>(Wq, Wk, Wv, Wo, gwf);

    dim3 gg(Dd / 64, Mm / 128);       // (12, 64)
    gemm2<<<gg, 256>>>(q, gwf,                  bq, gq,  1);
    gemm2<<<gg, 256>>>(k, gwf + (size_t)Dd*Dd,  bk, gkf, 2);
    gemm2<<<gg, 256>>>(v, gwf + (size_t)2*Dd*Dd, bv, gvf, 3);

    attn_mma2<<<dim3(Ss / 64, Bb * Hh), 128, smem_attn>>>(gq, gkf, gvf, gf);

    gemm2<<<gg, 256>>>(gf, gwf + (size_t)3*Dd*Dd, bo, out, 0);
}